// round 17
// baseline (speedup 1.0000x reference)
#include <cuda_runtime.h>
#include <cuda_fp16.h>
#include <cstdint>

#define N_NODES 50000
#define N_EDGES 800000
#define HDIM    128
#define N_RELS  24
#define M_TILES 391          /* ceil(50000/128) */
#define NMAT    25           /* 24 relations + self-loop */
#define NKEYS   (N_RELS * N_NODES)          /* 1,200,000 */
#define MAXROWS (N_RELS * M_TILES * 128)    /* worst-case padded compact rows */

// ---------------- scratch (device globals; no allocation allowed) ----------------
__device__ __half g_Hc[(size_t)MAXROWS * HDIM];           // 307 MB worst case
__device__ __half g_Hself[(size_t)N_NODES * HDIM];        // 12.8 MB
__device__ int   g_mark[NKEYS];                           // (rel,src) -> compact row+1
__device__ int   g_rows[MAXROWS];                         // compact row -> src
__device__ int   g_relcnt[N_RELS];
__device__ int   g_reloff[N_RELS];
__device__ int   g_deg[N_NODES];
__device__ int   g_cursor[N_NODES];
__device__ int   g_off[N_NODES + 1];
__device__ int   g_ekey[N_EDGES];                         // compact row idx, grouped by dst

// W^T as fp16, (n,k) row-major per matrix (k contiguous); slot 24 = W_loop
__device__ __half g_Bh[(size_t)NMAT * HDIM * HDIM];       // 0.8 MB

// ---------------- smem layout for GEMM (padded rows: 272 B = 136 fp16) ----------
#define ROWB    272
#define TILE_B  (128 * ROWB)            /* 34816 bytes per 128x128 fp16 tile */
#define SROWS   0                        /* 512 B: row indices */
#define SA      512
#define SB      (512 + TILE_B)
#define SM_TOTAL (512 + 2 * TILE_B)     /* 70144 */

// ================= helpers =================
#define CP_COMMIT()  asm volatile("cp.async.commit_group;" ::: "memory")
#define CP_WAIT0()   asm volatile("cp.async.wait_group 0;" ::: "memory")

__device__ __forceinline__ uint32_t smem_u32(const void* p) {
    uint32_t a;
    asm("{ .reg .u64 t; cvta.to.shared.u64 t, %1; cvt.u32.u64 %0, t; }" : "=r"(a) : "l"(p));
    return a;
}
__device__ __forceinline__ void cp16s(uint32_t dst_smem, const void* src) {
    asm volatile("cp.async.cg.shared.global [%0], [%1], 16;" :: "r"(dst_smem), "l"(src));
}
__device__ __forceinline__ void ldsm_x4(uint32_t& r0, uint32_t& r1, uint32_t& r2, uint32_t& r3,
                                        uint32_t addr) {
    asm volatile("ldmatrix.sync.aligned.m8n8.x4.shared.b16 {%0,%1,%2,%3}, [%4];"
                 : "=r"(r0), "=r"(r1), "=r"(r2), "=r"(r3) : "r"(addr));
}
__device__ __forceinline__ void mma16816(float* c, const uint32_t* a, const uint32_t* b) {
    asm volatile(
        "mma.sync.aligned.m16n8k16.row.col.f32.f16.f16.f32 "
        "{%0,%1,%2,%3}, {%4,%5,%6,%7}, {%8,%9}, {%0,%1,%2,%3};"
        : "+f"(c[0]), "+f"(c[1]), "+f"(c[2]), "+f"(c[3])
        : "r"(a[0]), "r"(a[1]), "r"(a[2]), "r"(a[3]), "r"(b[0]), "r"(b[1]));
}

// ---------------- conv B: g_Bh[r][n][k] = fp16(W[r][k][n]) ----------------------
__global__ void k_convB(const float* __restrict__ W, const float* __restrict__ W_loop) {
    int idx = blockIdx.x * blockDim.x + threadIdx.x;
    if (idx >= NMAT * 4096) return;
    int r = idx >> 12, q = idx & 4095;
    int n = q >> 5, c4 = q & 31;
    const float* Wsrc = (r < N_RELS) ? (W + (size_t)r * HDIM * HDIM) : W_loop;
    float4 v;
    v.x = Wsrc[(size_t)(c4 * 4 + 0) * HDIM + n];
    v.y = Wsrc[(size_t)(c4 * 4 + 1) * HDIM + n];
    v.z = Wsrc[(size_t)(c4 * 4 + 2) * HDIM + n];
    v.w = Wsrc[(size_t)(c4 * 4 + 3) * HDIM + n];
    __half2 h0 = __floats2half2_rn(v.x, v.y);
    __half2 h1 = __floats2half2_rn(v.z, v.w);
    size_t off = (size_t)r * HDIM * HDIM + (size_t)n * HDIM + c4 * 4;
    *(uint2*)(g_Bh + off) = make_uint2(*(uint32_t*)&h0, *(uint32_t*)&h1);
}

// ---------------- compaction pipeline ----------------
__global__ void k_mark(const int* __restrict__ src, const int* __restrict__ rel) {
    int i = blockIdx.x * blockDim.x + threadIdx.x;
    if (i < N_EDGES) g_mark[rel[i] * N_NODES + src[i]] = 1;
}

__global__ void k_assign() {
    __shared__ int s_cnt[N_RELS], s_base[N_RELS];
    int tid = threadIdx.x;
    if (tid < N_RELS) s_cnt[tid] = 0;
    __syncthreads();
    int key = blockIdx.x * 256 + tid;
    int m = (key < NKEYS) ? g_mark[key] : 0;
    int rel = 0, lp = 0;
    if (m) {
        rel = key / N_NODES;
        lp = atomicAdd(&s_cnt[rel], 1);
    }
    __syncthreads();
    if (tid < N_RELS && s_cnt[tid] > 0)
        s_base[tid] = atomicAdd(&g_relcnt[tid], s_cnt[tid]);
    __syncthreads();
    if (m) g_mark[key] = s_base[rel] + lp + 1;   // local-rel index + 1
}

__global__ void k_reloff() {
    if (threadIdx.x == 0) {
        int off = 0;
        for (int r = 0; r < N_RELS; r++) {
            g_reloff[r] = off;
            off += ((g_relcnt[r] + 127) >> 7) << 7;   // pad to 128-row tiles
        }
    }
}

__global__ void k_fillrows() {
    int key = blockIdx.x * 256 + threadIdx.x;
    if (key >= NKEYS) return;
    int m = g_mark[key];
    if (m) {
        int rel = key / N_NODES;
        int srcv = key - rel * N_NODES;
        int gpos = g_reloff[rel] + m - 1;
        g_rows[gpos] = srcv;
        g_mark[key] = gpos + 1;                  // global compact row + 1
    }
}

// ---------------- degree histogram ----------------
__global__ void k_deg(const int* __restrict__ dst) {
    int i = blockIdx.x * blockDim.x + threadIdx.x;
    if (i < N_EDGES) atomicAdd(&g_deg[dst[i]], 1);
}

// ---------------- single-block exclusive scan over g_deg -> g_off ----------------
__global__ void k_scan() {
    __shared__ int sbuf[1024];
    __shared__ int s_carry;
    int tid = threadIdx.x;
    if (tid == 0) s_carry = 0;
    __syncthreads();
    const int CH = 8192;
    for (int base = 0; base < N_NODES; base += CH) {
        int idx0 = base + tid * 8;
        int v[8];
        int s = 0;
#pragma unroll
        for (int j = 0; j < 8; j++) {
            v[j] = (idx0 + j < N_NODES) ? g_deg[idx0 + j] : 0;
            s += v[j];
        }
        sbuf[tid] = s;
        __syncthreads();
        for (int off = 1; off < 1024; off <<= 1) {
            int t2 = (tid >= off) ? sbuf[tid - off] : 0;
            __syncthreads();
            sbuf[tid] += t2;
            __syncthreads();
        }
        int excl = s_carry + sbuf[tid] - s;
#pragma unroll
        for (int j = 0; j < 8; j++) {
            if (idx0 + j < N_NODES) g_off[idx0 + j] = excl;
            excl += v[j];
        }
        __syncthreads();
        if (tid == 1023) s_carry += sbuf[1023];
        __syncthreads();
    }
    if (tid == 0) g_off[N_NODES] = s_carry;
}

// ---------------- scatter edges into CSR-by-dst (stores compact row idx) --------
__global__ void k_scatter(const int* __restrict__ src, const int* __restrict__ dst,
                          const int* __restrict__ rel) {
    int i = blockIdx.x * blockDim.x + threadIdx.x;
    if (i < N_EDGES) {
        int d = dst[i];
        int p = g_off[d] + atomicAdd(&g_cursor[d], 1);
        g_ekey[p] = g_mark[rel[i] * N_NODES + src[i]] - 1;
    }
}

// ---- compact GEMM: CTA = one 128-row compact tile of one relation --------------
__global__ __launch_bounds__(256, 2) void k_gemm_compact(const float* __restrict__ h) {
    extern __shared__ char smem[];
    const uint32_t sbase = smem_u32(smem);
    const int tid = threadIdx.x;
    const int rel = blockIdx.y;
    const int x = blockIdx.x;

    const int cnt = g_relcnt[rel];
    const int ntiles = (cnt + 127) >> 7;
    if (x >= ntiles) return;
    const int base = g_reloff[rel] + x * 128;

    // B cp.async (32 KB) early
    {
        const char* gb = (const char*)g_Bh + (size_t)rel * 32768;
        for (int q = tid; q < 2048; q += 256) {
            int row = q >> 4, seg = q & 15;
            cp16s(sbase + SB + row * ROWB + seg * 16, gb + row * 256 + seg * 16);
        }
        CP_COMMIT();
    }

    // row indices
    int* s_rows = (int*)(smem + SROWS);
    if (tid < 128) s_rows[tid] = g_rows[base + tid];
    __syncthreads();

    // gather + convert A (fp32 -> fp16) into padded smem
    for (int q = tid; q < 4096; q += 256) {
        int row = q >> 5, c4 = q & 31;
        int srcrow = s_rows[row];
        float4 v = ((const float4*)(h + (size_t)srcrow * HDIM))[c4];
        __half2 h0 = __floats2half2_rn(v.x, v.y);
        __half2 h1 = __floats2half2_rn(v.z, v.w);
        *(uint2*)(smem + SA + row * ROWB + c4 * 8) = make_uint2(*(uint32_t*)&h0, *(uint32_t*)&h1);
    }
    CP_WAIT0();
    __syncthreads();

    const int lane = tid & 31, wid = tid >> 5;
    const int g = lane >> 2, t = lane & 3;
    const int wm = (wid & 1) * 64;
    const int wn = (wid >> 1) * 32;
    const int a_row = wm + (lane & 15);
    const int a_kb  = (lane & 16) ? 16 : 0;
    const int b_n   = wn + ((lane >> 4) & 1) * 8 + (lane & 7);
    const int b_kb  = (lane & 8) ? 16 : 0;

    const uint32_t Ab = sbase + SA;
    const uint32_t Bb = sbase + SB;

    float acc[4][4][4];
#pragma unroll
    for (int mi = 0; mi < 4; mi++)
#pragma unroll
        for (int ni = 0; ni < 4; ni++)
#pragma unroll
            for (int c = 0; c < 4; c++) acc[mi][ni][c] = 0.f;

#pragma unroll
    for (int ks = 0; ks < 8; ks++) {
        const int kb = ks * 32;
        uint32_t a[4][4];
#pragma unroll
        for (int mi = 0; mi < 4; mi++)
            ldsm_x4(a[mi][0], a[mi][1], a[mi][2], a[mi][3],
                    Ab + (a_row + mi * 16) * ROWB + kb + a_kb);
        uint32_t b[4][2];
#pragma unroll
        for (int nh = 0; nh < 2; nh++)
            ldsm_x4(b[nh * 2][0], b[nh * 2][1], b[nh * 2 + 1][0], b[nh * 2 + 1][1],
                    Bb + (b_n + nh * 16) * ROWB + kb + b_kb);
#pragma unroll
        for (int mi = 0; mi < 4; mi++)
#pragma unroll
            for (int ni = 0; ni < 4; ni++)
                mma16816(acc[mi][ni], a[mi], b[ni]);
    }

    // store compact rows (contiguous, coalesced)
#pragma unroll
    for (int mi = 0; mi < 4; mi++) {
        int row0 = base + wm + mi * 16 + g;
#pragma unroll
        for (int ni = 0; ni < 4; ni++) {
            int col = wn + ni * 8 + 2 * t;
            __half2 p0 = __floats2half2_rn(acc[mi][ni][0], acc[mi][ni][1]);
            *(uint32_t*)(g_Hc + (size_t)row0 * HDIM + col) = *(uint32_t*)&p0;
            __half2 p1 = __floats2half2_rn(acc[mi][ni][2], acc[mi][ni][3]);
            *(uint32_t*)(g_Hc + (size_t)(row0 + 8) * HDIM + col) = *(uint32_t*)&p1;
        }
    }
}

// ---- self-loop GEMM: h @ W_loop -> g_Hself -------------------------------------
__global__ __launch_bounds__(256, 2) void k_gemm_self(const float* __restrict__ h) {
    extern __shared__ char smem[];
    const uint32_t sbase = smem_u32(smem);
    const int tid = threadIdx.x;
    const int m0 = blockIdx.x * 128;

    {
        const char* gb = (const char*)g_Bh + (size_t)N_RELS * 32768;
        for (int q = tid; q < 2048; q += 256) {
            int row = q >> 4, seg = q & 15;
            cp16s(sbase + SB + row * ROWB + seg * 16, gb + row * 256 + seg * 16);
        }
        CP_COMMIT();
    }

    for (int q = tid; q < 4096; q += 256) {
        int row = q >> 5, c4 = q & 31;
        float4 v = make_float4(0.f, 0.f, 0.f, 0.f);
        if (m0 + row < N_NODES) v = ((const float4*)(h + (size_t)(m0 + row) * HDIM))[c4];
        __half2 h0 = __floats2half2_rn(v.x, v.y);
        __half2 h1 = __floats2half2_rn(v.z, v.w);
        *(uint2*)(smem + SA + row * ROWB + c4 * 8) = make_uint2(*(uint32_t*)&h0, *(uint32_t*)&h1);
    }
    CP_WAIT0();
    __syncthreads();

    const int lane = tid & 31, wid = tid >> 5;
    const int g = lane >> 2, t = lane & 3;
    const int wm = (wid & 1) * 64;
    const int wn = (wid >> 1) * 32;
    const int a_row = wm + (lane & 15);
    const int a_kb  = (lane & 16) ? 16 : 0;
    const int b_n   = wn + ((lane >> 4) & 1) * 8 + (lane & 7);
    const int b_kb  = (lane & 8) ? 16 : 0;

    const uint32_t Ab = sbase + SA;
    const uint32_t Bb = sbase + SB;

    float acc[4][4][4];
#pragma unroll
    for (int mi = 0; mi < 4; mi++)
#pragma unroll
        for (int ni = 0; ni < 4; ni++)
#pragma unroll
            for (int c = 0; c < 4; c++) acc[mi][ni][c] = 0.f;

#pragma unroll
    for (int ks = 0; ks < 8; ks++) {
        const int kb = ks * 32;
        uint32_t a[4][4];
#pragma unroll
        for (int mi = 0; mi < 4; mi++)
            ldsm_x4(a[mi][0], a[mi][1], a[mi][2], a[mi][3],
                    Ab + (a_row + mi * 16) * ROWB + kb + a_kb);
        uint32_t b[4][2];
#pragma unroll
        for (int nh = 0; nh < 2; nh++)
            ldsm_x4(b[nh * 2][0], b[nh * 2][1], b[nh * 2 + 1][0], b[nh * 2 + 1][1],
                    Bb + (b_n + nh * 16) * ROWB + kb + b_kb);
#pragma unroll
        for (int mi = 0; mi < 4; mi++)
#pragma unroll
            for (int ni = 0; ni < 4; ni++)
                mma16816(acc[mi][ni], a[mi], b[ni]);
    }

#pragma unroll
    for (int mi = 0; mi < 4; mi++) {
        int row0 = m0 + wm + mi * 16 + g;
#pragma unroll
        for (int ni = 0; ni < 4; ni++) {
            int col = wn + ni * 8 + 2 * t;
            if (row0 < N_NODES) {
                __half2 p = __floats2half2_rn(acc[mi][ni][0], acc[mi][ni][1]);
                *(uint32_t*)(g_Hself + (size_t)row0 * HDIM + col) = *(uint32_t*)&p;
            }
            if (row0 + 8 < N_NODES) {
                __half2 p = __floats2half2_rn(acc[mi][ni][2], acc[mi][ni][3]);
                *(uint32_t*)(g_Hself + (size_t)(row0 + 8) * HDIM + col) = *(uint32_t*)&p;
            }
        }
    }
}

// ---------------- aggregation: warp per node; mean + self-loop + bias + relu ------
__device__ __forceinline__ void add4(float4& acc, uint2 u) {
    float2 lo = __half22float2(*(__half2*)&u.x);
    float2 hi = __half22float2(*(__half2*)&u.y);
    acc.x += lo.x; acc.y += lo.y; acc.z += hi.x; acc.w += hi.y;
}

__global__ void k_aggregate(const float* __restrict__ bias, float* __restrict__ out) {
    int warp = (blockIdx.x * blockDim.x + threadIdx.x) >> 5;
    int lane = threadIdx.x & 31;
    if (warp >= N_NODES) return;
    int beg = g_off[warp], end = g_off[warp + 1];
    float4 acc = make_float4(0.f, 0.f, 0.f, 0.f);
    int e = beg;
    for (; e + 1 < end; e += 2) {
        int k0 = g_ekey[e], k1 = g_ekey[e + 1];
        uint2 u0 = ((const uint2*)(g_Hc + (size_t)k0 * HDIM))[lane];
        uint2 u1 = ((const uint2*)(g_Hc + (size_t)k1 * HDIM))[lane];
        add4(acc, u0);
        add4(acc, u1);
    }
    if (e < end) {
        int k0 = g_ekey[e];
        uint2 u0 = ((const uint2*)(g_Hc + (size_t)k0 * HDIM))[lane];
        add4(acc, u0);
    }
    float scale = (end > beg) ? (1.0f / (float)(end - beg)) : 0.0f;
    uint2 su = ((const uint2*)(g_Hself + (size_t)warp * HDIM))[lane];
    float2 slo = __half22float2(*(__half2*)&su.x);
    float2 shi = __half22float2(*(__half2*)&su.y);
    float4 b = ((const float4*)bias)[lane];
    float4 o;
    o.x = fmaxf(fmaf(acc.x, scale, slo.x + b.x), 0.f);
    o.y = fmaxf(fmaf(acc.y, scale, slo.y + b.y), 0.f);
    o.z = fmaxf(fmaf(acc.z, scale, shi.x + b.z), 0.f);
    o.w = fmaxf(fmaf(acc.w, scale, shi.y + b.w), 0.f);
    ((float4*)out)[(size_t)warp * 32 + lane] = o;
}

// ---------------- launch ----------------
extern "C" void kernel_launch(void* const* d_in, const int* in_sizes, int n_in,
                              void* d_out, int out_size) {
    const float* h      = (const float*)d_in[0];
    const float* W      = (const float*)d_in[1];
    const float* W_loop = (const float*)d_in[2];
    const float* bias   = (const float*)d_in[3];
    const int*   src    = (const int*)d_in[4];
    const int*   dst    = (const int*)d_in[5];
    const int*   rel    = (const int*)d_in[6];
    float* out = (float*)d_out;

    void *p_deg, *p_cur, *p_mark, *p_relcnt;
    cudaGetSymbolAddress(&p_deg, g_deg);
    cudaGetSymbolAddress(&p_cur, g_cursor);
    cudaGetSymbolAddress(&p_mark, g_mark);
    cudaGetSymbolAddress(&p_relcnt, g_relcnt);
    cudaMemsetAsync(p_deg, 0, N_NODES * sizeof(int));
    cudaMemsetAsync(p_cur, 0, N_NODES * sizeof(int));
    cudaMemsetAsync(p_mark, 0, NKEYS * sizeof(int));
    cudaMemsetAsync(p_relcnt, 0, N_RELS * sizeof(int));

    cudaFuncSetAttribute(k_gemm_compact, cudaFuncAttributeMaxDynamicSharedMemorySize, SM_TOTAL);
    cudaFuncSetAttribute(k_gemm_self, cudaFuncAttributeMaxDynamicSharedMemorySize, SM_TOTAL);

    const int EB = (N_EDGES + 255) / 256;
    const int KB = (NKEYS + 255) / 256;

    k_deg<<<EB, 256>>>(dst);
    k_mark<<<EB, 256>>>(src, rel);
    k_assign<<<KB, 256>>>();
    k_reloff<<<1, 32>>>();
    k_fillrows<<<KB, 256>>>();
    k_scan<<<1, 1024>>>();
    k_scatter<<<EB, 256>>>(src, dst, rel);

    k_convB<<<(NMAT * 4096 + 255) / 256, 256>>>(W, W_loop);

    dim3 cgrid(M_TILES, N_RELS);
    k_gemm_compact<<<cgrid, 256, SM_TOTAL>>>(h);
    k_gemm_self<<<M_TILES, 256, SM_TOTAL>>>(h);

    int agg_blocks = (N_NODES * 32 + 255) / 256;
    k_aggregate<<<agg_blocks, 256>>>(bias, out);
}